// round 1
// baseline (speedup 1.0000x reference)
#include <cuda_runtime.h>
#include <cuda_bf16.h>
#include <cstdint>

// Problem constants (fixed by the dataset)
#define N_NODES    100000
#define N_FEAT     512
#define N_HID      256
// E comes from in_sizes[1] at launch.

// Scratch for h = x @ W^T + b : [N_NODES, N_HID] fp32 (102.4 MB, static device global)
__device__ float g_h[(size_t)N_NODES * N_HID];

// ---------------------------------------------------------------------------
// Kernel 1: SGEMM with bias.  C[M,N] = A[M,K] * B[N,K]^T + bias[N]
// A = x (row-major, K contiguous), B = W (row-major, K contiguous) -> NT gemm.
// Classic 128x128x8 tile, 256 threads, 8x8 per-thread microtile.
// ---------------------------------------------------------------------------
#define BM 128
#define BN 128
#define BK 8
#define TM 8
#define TN 8

__global__ __launch_bounds__(256, 2)
void gemm_bias_kernel(const float* __restrict__ A,
                      const float* __restrict__ B,
                      const float* __restrict__ bias,
                      float* __restrict__ C,
                      int M, int N, int K)
{
    __shared__ float As[BK][BM];
    __shared__ float Bs[BK][BN];

    const int tid = threadIdx.x;              // 0..255
    const int block_row = blockIdx.x * BM;
    const int block_col = blockIdx.y * BN;

    // Global-load mapping: 256 threads * float4 = 1024 floats = one 128x8 tile.
    const int ld_row  = tid >> 1;             // 0..127
    const int ld_col4 = (tid & 1) * 4;        // 0 or 4

    // Compute mapping: 16x16 thread grid, each 8x8.
    const int ty = (tid >> 4) * TM;           // 0..120
    const int tx = (tid & 15) * TN;           // 0..120

    float acc[TM][TN];
#pragma unroll
    for (int i = 0; i < TM; i++)
#pragma unroll
        for (int j = 0; j < TN; j++) acc[i][j] = 0.f;

    for (int k0 = 0; k0 < K; k0 += BK) {
        // Load A tile (guard M tail)
        float4 av = make_float4(0.f, 0.f, 0.f, 0.f);
        {
            int gr = block_row + ld_row;
            if (gr < M)
                av = *(const float4*)(A + (size_t)gr * K + k0 + ld_col4);
        }
        As[ld_col4 + 0][ld_row] = av.x;
        As[ld_col4 + 1][ld_row] = av.y;
        As[ld_col4 + 2][ld_row] = av.z;
        As[ld_col4 + 3][ld_row] = av.w;

        // Load B tile (N=256 exactly covered by 2 column blocks, no guard)
        float4 bv = *(const float4*)(B + (size_t)(block_col + ld_row) * K + k0 + ld_col4);
        Bs[ld_col4 + 0][ld_row] = bv.x;
        Bs[ld_col4 + 1][ld_row] = bv.y;
        Bs[ld_col4 + 2][ld_row] = bv.z;
        Bs[ld_col4 + 3][ld_row] = bv.w;

        __syncthreads();

#pragma unroll
        for (int k = 0; k < BK; k++) {
            float ar[TM], br[TN];
#pragma unroll
            for (int i = 0; i < TM; i++) ar[i] = As[k][ty + i];
#pragma unroll
            for (int j = 0; j < TN; j++) br[j] = Bs[k][tx + j];
#pragma unroll
            for (int i = 0; i < TM; i++)
#pragma unroll
                for (int j = 0; j < TN; j++)
                    acc[i][j] = fmaf(ar[i], br[j], acc[i][j]);
        }
        __syncthreads();
    }

    // Epilogue: add bias, store (vectorized float4 along N)
#pragma unroll
    for (int i = 0; i < TM; i++) {
        int row = block_row + ty + i;
        if (row >= M) continue;
#pragma unroll
        for (int j = 0; j < TN; j += 4) {
            int col = block_col + tx + j;
            float4 v;
            v.x = acc[i][j + 0] + bias[col + 0];
            v.y = acc[i][j + 1] + bias[col + 1];
            v.z = acc[i][j + 2] + bias[col + 2];
            v.w = acc[i][j + 3] + bias[col + 3];
            *(float4*)(C + (size_t)row * N + col) = v;
        }
    }
}

// ---------------------------------------------------------------------------
// Kernel 2: edge-parallel SpMM scatter.
// One warp per edge: gather h[col] (256 f32 = 64 float4, 2 per lane), scale by
// val, red.global.add.v4.f32 into out[row].
// ---------------------------------------------------------------------------
__device__ __forceinline__ void red_add_v4(float* addr, float4 v)
{
    asm volatile("red.global.add.v4.f32 [%0], {%1, %2, %3, %4};"
                 :: "l"(addr), "f"(v.x), "f"(v.y), "f"(v.z), "f"(v.w)
                 : "memory");
}

__global__ __launch_bounds__(256)
void spmm_scatter_kernel(const int*   __restrict__ rows,
                         const int*   __restrict__ cols,
                         const float* __restrict__ vals,
                         float*       __restrict__ out,
                         int E)
{
    const int warp_id = (blockIdx.x * blockDim.x + threadIdx.x) >> 5;
    const int lane    = threadIdx.x & 31;
    if (warp_id >= E) return;

    const int   r = rows[warp_id];
    const int   c = cols[warp_id];
    const float v = vals[warp_id];

    const float4* src = (const float4*)(g_h + (size_t)c * N_HID);
    float* dst = out + (size_t)r * N_HID;

    float4 a = __ldg(&src[lane]);
    float4 b = __ldg(&src[lane + 32]);

    a.x *= v; a.y *= v; a.z *= v; a.w *= v;
    b.x *= v; b.y *= v; b.z *= v; b.w *= v;

    red_add_v4(dst + lane * 4,        a);
    red_add_v4(dst + (lane + 32) * 4, b);
}

// ---------------------------------------------------------------------------
// Kernel 3: in-place PReLU over the aggregated output.
// ---------------------------------------------------------------------------
__global__ __launch_bounds__(256)
void prelu_kernel(float* __restrict__ out, const float* __restrict__ alpha_p,
                  int n4)
{
    const float alpha = *alpha_p;
    int i = blockIdx.x * blockDim.x + threadIdx.x;
    if (i >= n4) return;
    float4 v = ((float4*)out)[i];
    v.x = v.x >= 0.f ? v.x : alpha * v.x;
    v.y = v.y >= 0.f ? v.y : alpha * v.y;
    v.z = v.z >= 0.f ? v.z : alpha * v.z;
    v.w = v.w >= 0.f ? v.w : alpha * v.w;
    ((float4*)out)[i] = v;
}

// ---------------------------------------------------------------------------
// Launch
// ---------------------------------------------------------------------------
extern "C" void kernel_launch(void* const* d_in, const int* in_sizes, int n_in,
                              void* d_out, int out_size)
{
    const float* x     = (const float*)d_in[0];   // [1, N_NODES, N_FEAT]
    const int*   rows  = (const int*)  d_in[1];   // [E]
    const int*   cols  = (const int*)  d_in[2];   // [E]
    const float* vals  = (const float*)d_in[3];   // [E]
    const float* W     = (const float*)d_in[4];   // [N_HID, N_FEAT]
    const float* b     = (const float*)d_in[5];   // [N_HID]
    const float* alpha = (const float*)d_in[6];   // scalar

    float* out = (float*)d_out;                   // [1, N_NODES, N_HID]
    const int E = in_sizes[1];

    float* h;
    cudaGetSymbolAddress((void**)&h, g_h);

    // 1) h = x @ W^T + b
    dim3 ggrid((N_NODES + BM - 1) / BM, N_HID / BN);
    gemm_bias_kernel<<<ggrid, 256>>>(x, W, b, h, N_NODES, N_HID, N_FEAT);

    // 2) zero the output accumulator (d_out is poisoned)
    cudaMemsetAsync(d_out, 0, (size_t)out_size * sizeof(float));

    // 3) edge scatter: one warp per edge, 8 warps per block
    int nblocks = (E + 7) / 8;
    spmm_scatter_kernel<<<nblocks, 256>>>(rows, cols, vals, out, E);

    // 4) PReLU in place
    int n4 = out_size / 4;
    prelu_kernel<<<(n4 + 255) / 256, 256>>>(out, alpha, n4);
}